// round 2
// baseline (speedup 1.0000x reference)
#include <cuda_runtime.h>
#include <cstddef>

#define HH 128
#define WW 128
#define HW 16384
#define BB 4

// ---------------- scratch (static device globals; no allocation) ----------------
__device__ float g_multi[(size_t)BB * 768 * HW];    // qkv (0..383) + ms (384..767)
__device__ float g_msdw[(size_t)BB * 384 * HW];     // depthwise 5x5 output
__device__ float g_att[(size_t)BB * 256 * HW];      // attention output
__device__ float g_attended[(size_t)BB * 128 * HW]; // residual branch point
__device__ float g_h1[(size_t)BB * 768 * HW];       // mb1 output
__device__ float g_h2[(size_t)BB * 768 * HW];       // mb2 output
__device__ float g_kv[(size_t)BB * 32 * 72];        // per-(b,g) 9x8 kv matrices
__device__ float g_wT[768 * 1152];                  // transposed weights scratch

// ---------------- weight transpose: w[co][k] -> wT[k][co] ----------------
__global__ void transpose_k(const float* __restrict__ w, float* __restrict__ wT,
                            int Cout, int Cin) {
    int idx = blockIdx.x * 256 + threadIdx.x;
    if (idx < Cout * Cin) {
        int co = idx / Cin;
        int ci = idx - co * Cin;
        wT[(size_t)ci * Cout + co] = w[idx];
    }
}

// ---------------- 3x3 conv, Cin=128 -> Cout=128, SAME pad, bias ----------------
// wT layout: [ci*9+rs][128].  out written into g_multi at channel offset outOff (Ctot=768).
__global__ void conv3x3_k(const float* __restrict__ in, const float* __restrict__ wT,
                          const float* __restrict__ bias, float* __restrict__ out,
                          int outOff) {
    __shared__ float Wsh[72][64];
    __shared__ float Ish[8][3][68];
    int tid = threadIdx.x;
    int tx = tid & 15, ty = tid >> 4;
    int xbase = blockIdx.x * 64;
    int y = blockIdx.y;
    int b = blockIdx.z >> 1;
    int cbase = (blockIdx.z & 1) * 64;
    const float* inB = in + (size_t)b * 128 * HW;
    float acc[4][4] = {};

    for (int c0 = 0; c0 < 128; c0 += 8) {
        __syncthreads();
        // weights: 72x64 = 4608, coalesced (consecutive oc)
        for (int i = tid; i < 4608; i += 256) {
            int k = i >> 6;
            int oc = i & 63;
            Wsh[k][oc] = wT[(size_t)(c0 * 9 + k) * 128 + cbase + oc];
        }
        // input patch: 8 ch x 3 rows x 66 cols (halo, zero pad)
        for (int i = tid; i < 8 * 3 * 66; i += 256) {
            int col = i % 66;
            int t = i / 66;
            int r = t % 3;
            int c = t / 3;
            int xx = xbase - 1 + col;
            int yy = y - 1 + r;
            float v = 0.f;
            if (xx >= 0 && xx < WW && yy >= 0 && yy < HH)
                v = inB[(size_t)(c0 + c) * HW + yy * WW + xx];
            Ish[c][r][col] = v;
        }
        __syncthreads();
#pragma unroll
        for (int c = 0; c < 8; c++) {
#pragma unroll
            for (int r = 0; r < 3; r++) {
#pragma unroll
                for (int s = 0; s < 3; s++) {
                    float4 wv = *(const float4*)&Wsh[c * 9 + r * 3 + s][ty * 4];
                    float v0 = Ish[c][r][tx + s];
                    float v1 = Ish[c][r][tx + 16 + s];
                    float v2 = Ish[c][r][tx + 32 + s];
                    float v3 = Ish[c][r][tx + 48 + s];
                    acc[0][0] += wv.x * v0; acc[0][1] += wv.x * v1; acc[0][2] += wv.x * v2; acc[0][3] += wv.x * v3;
                    acc[1][0] += wv.y * v0; acc[1][1] += wv.y * v1; acc[1][2] += wv.y * v2; acc[1][3] += wv.y * v3;
                    acc[2][0] += wv.z * v0; acc[2][1] += wv.z * v1; acc[2][2] += wv.z * v2; acc[2][3] += wv.z * v3;
                    acc[3][0] += wv.w * v0; acc[3][1] += wv.w * v1; acc[3][2] += wv.w * v2; acc[3][3] += wv.w * v3;
                }
            }
        }
    }
#pragma unroll
    for (int i = 0; i < 4; i++) {
        int co = cbase + ty * 4 + i;
        float bv = bias[co];
        float* op = out + ((size_t)b * 768 + outOff + co) * HW + y * WW + xbase;
#pragma unroll
        for (int p = 0; p < 4; p++)
            op[tx + p * 16] = acc[i][p] + bv;
    }
}

// ---------------- 5x5 depthwise on multi channels 0..383 -> msdw ----------------
__global__ void dw5x5_k(const float* __restrict__ in, const float* __restrict__ wgt,
                        float* __restrict__ out) {
    __shared__ float sh[5][136];
    int x = threadIdx.x;
    int y = blockIdx.x;
    int c = blockIdx.y;
    int b = blockIdx.z;
    const float* inC = in + ((size_t)b * 768 + c) * HW;
    for (int r = 0; r < 5; r++) {
        int yy = y - 2 + r;
        for (int i = x; i < 132; i += 128) {
            int xx = i - 2;
            float v = 0.f;
            if (yy >= 0 && yy < HH && xx >= 0 && xx < WW) v = inC[yy * WW + xx];
            sh[r][i] = v;
        }
    }
    __syncthreads();
    const float* wc = wgt + c * 25;
    float a = 0.f;
#pragma unroll
    for (int r = 0; r < 5; r++)
#pragma unroll
        for (int s = 0; s < 5; s++)
            a += wc[r * 5 + s] * sh[r][x + s];
    out[((size_t)b * 384 + c) * HW + y * WW + x] = a;
}

// ---------------- grouped 1x1, 8->8 per group, 48 groups; writes multi[384..767] ----------------
__global__ void pw_group_k(const float* __restrict__ in, const float* __restrict__ wgt,
                           float* __restrict__ out) {
    __shared__ float wsh[64];
    int g = blockIdx.y;
    int b = blockIdx.z;
    if (threadIdx.x < 64) wsh[threadIdx.x] = wgt[g * 64 + threadIdx.x];
    __syncthreads();
    int n = blockIdx.x * 128 + threadIdx.x;
    const float* ip = in + ((size_t)b * 384 + g * 8) * HW + n;
    float xi[8];
#pragma unroll
    for (int i = 0; i < 8; i++) xi[i] = ip[(size_t)i * HW];
    float* op = out + ((size_t)b * 768 + 384 + g * 8) * HW + n;
#pragma unroll
    for (int o = 0; o < 8; o++) {
        float a = 0.f;
#pragma unroll
        for (int i = 0; i < 8; i++) a += wsh[o * 8 + i] * xi[i];
        op[(size_t)o * HW] = a;
    }
}

// ---------------- zero kv accumulators ----------------
__global__ void zero_kv_k(float* __restrict__ kv) {
    int i = blockIdx.x * 256 + threadIdx.x;
    if (i < BB * 32 * 72) kv[i] = 0.f;
}

// ---------------- attention phase 1: kv[b][g][e][j] = sum_n vaug[e,n]*relu(k[j,n]) ----------------
__global__ void attn_kv_k(const float* __restrict__ multi, float* __restrict__ kv) {
    int b = blockIdx.z, g = blockIdx.y;
    const float* base = multi + ((size_t)b * 768 + g * 24) * HW;
    int n0 = blockIdx.x * 2048;
    float acc[72];
#pragma unroll
    for (int i = 0; i < 72; i++) acc[i] = 0.f;
    for (int n = n0 + threadIdx.x; n < n0 + 2048; n += 256) {
        float kq[8], vv[8];
#pragma unroll
        for (int j = 0; j < 8; j++) kq[j] = fmaxf(base[(size_t)(8 + j) * HW + n], 0.f);
#pragma unroll
        for (int e = 0; e < 8; e++) vv[e] = base[(size_t)(16 + e) * HW + n];
#pragma unroll
        for (int e = 0; e < 8; e++)
#pragma unroll
            for (int j = 0; j < 8; j++) acc[e * 8 + j] += vv[e] * kq[j];
#pragma unroll
        for (int j = 0; j < 8; j++) acc[64 + j] += kq[j];
    }
    __shared__ float red[72][8];
    int lane = threadIdx.x & 31, warp = threadIdx.x >> 5;
#pragma unroll
    for (int i = 0; i < 72; i++) {
        float v = acc[i];
        v += __shfl_down_sync(0xffffffffu, v, 16);
        v += __shfl_down_sync(0xffffffffu, v, 8);
        v += __shfl_down_sync(0xffffffffu, v, 4);
        v += __shfl_down_sync(0xffffffffu, v, 2);
        v += __shfl_down_sync(0xffffffffu, v, 1);
        if (lane == 0) red[i][warp] = v;
    }
    __syncthreads();
    if (threadIdx.x < 72) {
        float s = 0.f;
#pragma unroll
        for (int w = 0; w < 8; w++) s += red[threadIdx.x][w];
        atomicAdd(&kv[((size_t)b * 32 + g) * 72 + threadIdx.x], s);
    }
}

// ---------------- attention phase 2: out = (kv @ relu(q)) normalized ----------------
__global__ void attn_apply_k(const float* __restrict__ multi, const float* __restrict__ kv,
                             float* __restrict__ att) {
    int b = blockIdx.z, g = blockIdx.y;
    __shared__ float kvs[72];
    if (threadIdx.x < 72) kvs[threadIdx.x] = kv[((size_t)b * 32 + g) * 72 + threadIdx.x];
    __syncthreads();
    int n = blockIdx.x * 256 + threadIdx.x;
    const float* base = multi + ((size_t)b * 768 + g * 24) * HW + n;
    float q[8];
#pragma unroll
    for (int j = 0; j < 8; j++) q[j] = fmaxf(base[(size_t)j * HW], 0.f);
    float denom = 0.f;
#pragma unroll
    for (int j = 0; j < 8; j++) denom += kvs[64 + j] * q[j];
    float inv = 1.f / (denom + 1e-15f);
    float* op = att + ((size_t)b * 256 + g * 8) * HW + n;
#pragma unroll
    for (int e = 0; e < 8; e++) {
        float s = 0.f;
#pragma unroll
        for (int j = 0; j < 8; j++) s += kvs[e * 8 + j] * q[j];
        op[(size_t)e * HW] = s * inv;
    }
}

// ---------------- 1x1 conv (GEMM), tiled 64x64, epilogues ----------------
// MODE 0: out = hswish(acc + bias[co])                     (p0 = bias)
// MODE 1: out = res + bn(acc) with bn params p0..p3 (g,b,m,v)
template <int MODE>
__global__ void gemm1x1_k(const float* __restrict__ in, int Cin,
                          const float* __restrict__ wT, int Cout,
                          const float* __restrict__ p0, const float* __restrict__ p1,
                          const float* __restrict__ p2, const float* __restrict__ p3,
                          const float* __restrict__ res, float* __restrict__ out) {
    __shared__ float Wsh[16][64];
    __shared__ float Ish[16][64];
    int tid = threadIdx.x;
    int tx = tid & 15, ty = tid >> 4;
    int nbase = blockIdx.x * 64;
    int cb = blockIdx.y * 64;
    int b = blockIdx.z;
    const float* inB = in + (size_t)b * Cin * HW + nbase;
    float acc[4][4] = {};
    int kk = tid >> 4;  // 0..15 (row for float4 fill)
    int p4 = tid & 15;

    for (int k0 = 0; k0 < Cin; k0 += 16) {
        __syncthreads();
        ((float4*)Wsh)[tid] = ((const float4*)(wT + (size_t)(k0 + kk) * Cout + cb))[p4];
        ((float4*)Ish)[tid] = ((const float4*)(inB + (size_t)(k0 + kk) * HW))[p4];
        __syncthreads();
#pragma unroll
        for (int k = 0; k < 16; k++) {
            float4 wv = *(const float4*)&Wsh[k][ty * 4];
            float i0 = Ish[k][tx], i1 = Ish[k][tx + 16], i2 = Ish[k][tx + 32], i3 = Ish[k][tx + 48];
            acc[0][0] += wv.x * i0; acc[0][1] += wv.x * i1; acc[0][2] += wv.x * i2; acc[0][3] += wv.x * i3;
            acc[1][0] += wv.y * i0; acc[1][1] += wv.y * i1; acc[1][2] += wv.y * i2; acc[1][3] += wv.y * i3;
            acc[2][0] += wv.z * i0; acc[2][1] += wv.z * i1; acc[2][2] += wv.z * i2; acc[2][3] += wv.z * i3;
            acc[3][0] += wv.w * i0; acc[3][1] += wv.w * i1; acc[3][2] += wv.w * i2; acc[3][3] += wv.w * i3;
        }
    }
#pragma unroll
    for (int i = 0; i < 4; i++) {
        int co = cb + ty * 4 + i;
        size_t rowoff = ((size_t)b * Cout + co) * HW + nbase;
        float bias = 0.f, scale = 0.f, shift = 0.f;
        if (MODE == 0) {
            bias = p0[co];
        } else {
            scale = p0[co] * rsqrtf(p3[co] + 1e-5f);
            shift = p1[co] - p2[co] * scale;
        }
#pragma unroll
        for (int p = 0; p < 4; p++) {
            int col = tx + p * 16;
            float x = acc[i][p];
            float o;
            if (MODE == 0) {
                x += bias;
                o = x * fminf(fmaxf(x + 3.f, 0.f), 6.f) * (1.f / 6.f);
            } else {
                float v = x * scale + shift;
                o = res[rowoff + col] + v;
            }
            out[rowoff + col] = o;
        }
    }
}

// ---------------- 3x3 depthwise + bias + hswish (768 channels) ----------------
__global__ void dw3x3_k(const float* __restrict__ in, const float* __restrict__ wgt,
                        const float* __restrict__ bias, float* __restrict__ out) {
    __shared__ float sh[3][136];
    int x = threadIdx.x, y = blockIdx.x, c = blockIdx.y, b = blockIdx.z;
    const float* inC = in + ((size_t)b * 768 + c) * HW;
    for (int r = 0; r < 3; r++) {
        int yy = y - 1 + r;
        for (int i = x; i < 130; i += 128) {
            int xx = i - 1;
            float v = 0.f;
            if (yy >= 0 && yy < HH && xx >= 0 && xx < WW) v = inC[yy * WW + xx];
            sh[r][i] = v;
        }
    }
    __syncthreads();
    const float* wc = wgt + c * 9;
    float a = bias[c];
#pragma unroll
    for (int r = 0; r < 3; r++)
#pragma unroll
        for (int s = 0; s < 3; s++)
            a += wc[r * 3 + s] * sh[r][x + s];
    float o = a * fminf(fmaxf(a + 3.f, 0.f), 6.f) * (1.f / 6.f);
    out[((size_t)b * 768 + c) * HW + y * WW + x] = o;
}

// ---------------- launch ----------------
extern "C" void kernel_launch(void* const* d_in, const int* in_sizes, int n_in,
                              void* d_out, int out_size) {
    const float* ref = (const float*)d_in[0];
    const float* oth = (const float*)d_in[1];
    const float* wq = (const float*)d_in[2];
    const float* bq = (const float*)d_in[3];
    const float* wk = (const float*)d_in[4];
    const float* bk = (const float*)d_in[5];
    const float* wv = (const float*)d_in[6];
    const float* bv = (const float*)d_in[7];
    const float* agg_dw_w = (const float*)d_in[8];
    const float* agg_pw_w = (const float*)d_in[9];
    const float* attn_proj_w = (const float*)d_in[10];
    const float* bn1_g = (const float*)d_in[11];
    const float* bn1_b = (const float*)d_in[12];
    const float* bn1_m = (const float*)d_in[13];
    const float* bn1_v = (const float*)d_in[14];
    const float* mb1_w = (const float*)d_in[15];
    const float* mb1_b = (const float*)d_in[16];
    const float* mb2_w = (const float*)d_in[17];
    const float* mb2_b = (const float*)d_in[18];
    const float* mb3_w = (const float*)d_in[19];
    const float* bn2_g = (const float*)d_in[20];
    const float* bn2_b = (const float*)d_in[21];
    const float* bn2_m = (const float*)d_in[22];
    const float* bn2_v = (const float*)d_in[23];

    float *multi, *msdw, *att, *attended, *h1, *h2, *kv, *wT;
    cudaGetSymbolAddress((void**)&multi, g_multi);
    cudaGetSymbolAddress((void**)&msdw, g_msdw);
    cudaGetSymbolAddress((void**)&att, g_att);
    cudaGetSymbolAddress((void**)&attended, g_attended);
    cudaGetSymbolAddress((void**)&h1, g_h1);
    cudaGetSymbolAddress((void**)&h2, g_h2);
    cudaGetSymbolAddress((void**)&kv, g_kv);
    cudaGetSymbolAddress((void**)&wT, g_wT);

    // q, k, v  (3x3 convs) -> multi channels 0/128/256
    transpose_k<<<(128 * 1152 + 255) / 256, 256>>>(wq, wT, 128, 1152);
    conv3x3_k<<<dim3(2, 128, 8), 256>>>(ref, wT, bq, multi, 0);
    transpose_k<<<(128 * 1152 + 255) / 256, 256>>>(wk, wT, 128, 1152);
    conv3x3_k<<<dim3(2, 128, 8), 256>>>(oth, wT, bk, multi, 128);
    transpose_k<<<(128 * 1152 + 255) / 256, 256>>>(wv, wT, 128, 1152);
    conv3x3_k<<<dim3(2, 128, 8), 256>>>(oth, wT, bv, multi, 256);

    // aggregation: 5x5 dw then grouped 1x1 -> multi channels 384..767
    dw5x5_k<<<dim3(128, 384, 4), 128>>>(multi, agg_dw_w, msdw);
    pw_group_k<<<dim3(128, 48, 4), 128>>>(msdw, agg_pw_w, multi);

    // relu linear attention
    zero_kv_k<<<(BB * 32 * 72 + 255) / 256, 256>>>(kv);
    attn_kv_k<<<dim3(8, 32, 4), 256>>>(multi, kv);
    attn_apply_k<<<dim3(64, 32, 4), 256>>>(multi, kv, att);

    // attn_proj + bn1 + residual -> attended
    transpose_k<<<(128 * 256 + 255) / 256, 256>>>(attn_proj_w, wT, 128, 256);
    gemm1x1_k<1><<<dim3(256, 2, 4), 256>>>(att, 256, wT, 128, bn1_g, bn1_b, bn1_m, bn1_v,
                                           ref, attended);

    // MBConv
    transpose_k<<<(768 * 128 + 255) / 256, 256>>>(mb1_w, wT, 768, 128);
    gemm1x1_k<0><<<dim3(256, 12, 4), 256>>>(attended, 128, wT, 768, mb1_b, nullptr, nullptr,
                                            nullptr, nullptr, h1);
    dw3x3_k<<<dim3(128, 768, 4), 128>>>(h1, mb2_w, mb2_b, h2);
    transpose_k<<<(128 * 768 + 255) / 256, 256>>>(mb3_w, wT, 128, 768);
    gemm1x1_k<1><<<dim3(256, 2, 4), 256>>>(h2, 768, wT, 128, bn2_g, bn2_b, bn2_m, bn2_v,
                                           attended, (float*)d_out);
}

// round 5
// speedup vs baseline: 1.8128x; 1.8128x over previous
#include <cuda_runtime.h>
#include <cstdint>
#include <cstddef>

#define HH 128
#define WW 128
#define HW 16384
#define BB 4

// ---------------- scratch (static device globals; no allocation) ----------------
__device__ float g_multi[(size_t)BB * 768 * HW];    // qkv (0..383) + ms (384..767)
__device__ float g_msdw[(size_t)BB * 384 * HW];     // depthwise 5x5 output
__device__ float g_att[(size_t)BB * 256 * HW];      // attention output
__device__ float g_attended[(size_t)BB * 128 * HW]; // residual branch point
__device__ float g_h1[(size_t)BB * 768 * HW];       // mb1 output
__device__ float g_h2[(size_t)BB * 768 * HW];       // mb2 output
__device__ float g_kv[(size_t)BB * 32 * 72];        // per-(b,g) 9x8 kv matrices
__device__ float g_wT[768 * 1152];                  // transposed weights scratch

// ---------------- tf32 mma helpers ----------------
__device__ __forceinline__ uint32_t f2tf32(float f) {
    uint32_t u;
    asm("cvt.rna.tf32.f32 %0, %1;" : "=r"(u) : "f"(f));
    return u;
}

__device__ __forceinline__ void mma_tf32(float& d0, float& d1, float& d2, float& d3,
                                         uint32_t a0, uint32_t a1, uint32_t a2, uint32_t a3,
                                         uint32_t b0, uint32_t b1) {
    asm volatile(
        "mma.sync.aligned.m16n8k8.row.col.f32.tf32.tf32.f32 "
        "{%0,%1,%2,%3},{%4,%5,%6,%7},{%8,%9},{%0,%1,%2,%3};"
        : "+f"(d0), "+f"(d1), "+f"(d2), "+f"(d3)
        : "r"(a0), "r"(a1), "r"(a2), "r"(a3), "r"(b0), "r"(b1));
}

__device__ __forceinline__ float hswish_f(float x) {
    return x * fminf(fmaxf(x + 3.f, 0.f), 6.f) * (1.f / 6.f);
}

// ---------------- weight transpose: w[co][k] -> wT[k][co] ----------------
__global__ void transpose_k(const float* __restrict__ w, float* __restrict__ wT,
                            int Cout, int Cin) {
    int idx = blockIdx.x * 256 + threadIdx.x;
    if (idx < Cout * Cin) {
        int co = idx / Cin;
        int ci = idx - co * Cin;
        wT[(size_t)ci * Cout + co] = w[idx];
    }
}

// ---------------- 3x3 conv via tf32 tensor cores ----------------
// Block: 64 couts x 128 pixels (one image row). 8 warps arranged 2(M) x 4(N).
// wT layout: [ci*9+rs][128].
__global__ void conv3x3_tc(const float* __restrict__ in, const float* __restrict__ wT,
                           const float* __restrict__ bias, float* __restrict__ out,
                           int outOff) {
    __shared__ float Wsh[72][72];       // [cin8*9+rs][cout64 pad72]  stride%32==8
    __shared__ float Ish[8][3][136];    // [cin8][row3][col(-1..128) pad]
    int tid = threadIdx.x;
    int lane = tid & 31, warp = tid >> 5;
    int g = lane >> 2, t = lane & 3;
    int wm = (warp >> 2) * 32;          // warp M offset (0/32)
    int wn = (warp & 3) * 32;           // warp N offset (0..96)
    int y = blockIdx.x;
    int cbase = blockIdx.y * 64;
    int b = blockIdx.z;
    const float* inB = in + (size_t)b * 128 * HW;
    float acc[2][4][4] = {};

    for (int c0 = 0; c0 < 128; c0 += 8) {
        __syncthreads();
        for (int i = tid; i < 72 * 64; i += 256) {
            int k = i >> 6, oc = i & 63;
            Wsh[k][oc] = wT[(size_t)(c0 * 9 + k) * 128 + cbase + oc];
        }
        for (int i = tid; i < 8 * 3 * 130; i += 256) {
            int col = i % 130;
            int tr = i / 130;
            int r = tr % 3, c = tr / 3;
            int xx = col - 1, yy = y - 1 + r;
            float v = 0.f;
            if (xx >= 0 && xx < WW && yy >= 0 && yy < HH)
                v = inB[(size_t)(c0 + c) * HW + yy * WW + xx];
            Ish[c][r][col] = v;
        }
        __syncthreads();
#pragma unroll
        for (int r = 0; r < 3; r++) {
#pragma unroll
            for (int s = 0; s < 3; s++) {
                int rs = r * 3 + s;
                uint32_t a[2][4];
#pragma unroll
                for (int mi = 0; mi < 2; mi++) {
                    a[mi][0] = f2tf32(Wsh[t * 9 + rs][wm + mi * 16 + g]);
                    a[mi][1] = f2tf32(Wsh[t * 9 + rs][wm + mi * 16 + g + 8]);
                    a[mi][2] = f2tf32(Wsh[(t + 4) * 9 + rs][wm + mi * 16 + g]);
                    a[mi][3] = f2tf32(Wsh[(t + 4) * 9 + rs][wm + mi * 16 + g + 8]);
                }
#pragma unroll
                for (int ni = 0; ni < 4; ni++) {
                    uint32_t b0 = f2tf32(Ish[t][r][wn + ni * 8 + g + s]);
                    uint32_t b1 = f2tf32(Ish[t + 4][r][wn + ni * 8 + g + s]);
#pragma unroll
                    for (int mi = 0; mi < 2; mi++)
                        mma_tf32(acc[mi][ni][0], acc[mi][ni][1], acc[mi][ni][2], acc[mi][ni][3],
                                 a[mi][0], a[mi][1], a[mi][2], a[mi][3], b0, b1);
                }
            }
        }
    }
#pragma unroll
    for (int mi = 0; mi < 2; mi++) {
        int co0 = cbase + wm + mi * 16 + g;
        int co1 = co0 + 8;
        float bv0 = bias[co0], bv1 = bias[co1];
        float* p0 = out + ((size_t)b * 768 + outOff + co0) * HW + y * WW;
        float* p1 = out + ((size_t)b * 768 + outOff + co1) * HW + y * WW;
#pragma unroll
        for (int ni = 0; ni < 4; ni++) {
            int x0 = wn + ni * 8 + 2 * t;
            *(float2*)&p0[x0] = make_float2(acc[mi][ni][0] + bv0, acc[mi][ni][1] + bv0);
            *(float2*)&p1[x0] = make_float2(acc[mi][ni][2] + bv1, acc[mi][ni][3] + bv1);
        }
    }
}

// ---------------- 1x1 conv (GEMM) via tf32 tensor cores ----------------
// Block: 64 couts x 128 pixels. MODE 0: hswish(acc+bias). MODE 1: res + bn(acc).
template <int MODE>
__global__ void gemm1x1_tc(const float* __restrict__ in, int Cin,
                           const float* __restrict__ wT, int Cout,
                           const float* __restrict__ p0, const float* __restrict__ p1,
                           const float* __restrict__ p2, const float* __restrict__ p3,
                           const float* __restrict__ res, float* __restrict__ out) {
    __shared__ float Wsh[16][72];
    __shared__ float Ish[16][136];
    int tid = threadIdx.x;
    int lane = tid & 31, warp = tid >> 5;
    int g = lane >> 2, t = lane & 3;
    int wm = (warp >> 2) * 32;
    int wn = (warp & 3) * 32;
    int nbase = blockIdx.x * 128;
    int cb = blockIdx.y * 64;
    int b = blockIdx.z;
    const float* inB = in + (size_t)b * Cin * HW + nbase;
    float acc[2][4][4] = {};

    for (int k0 = 0; k0 < Cin; k0 += 16) {
        __syncthreads();
        {
            int k = tid >> 4, p = tid & 15;
            *(float4*)&Wsh[k][p * 4] = *(const float4*)&wT[(size_t)(k0 + k) * Cout + cb + p * 4];
            int k2 = tid >> 5, p2 = tid & 31;
            *(float4*)&Ish[k2][p2 * 4] = *(const float4*)&inB[(size_t)(k0 + k2) * HW + p2 * 4];
            *(float4*)&Ish[k2 + 8][p2 * 4] = *(const float4*)&inB[(size_t)(k0 + k2 + 8) * HW + p2 * 4];
        }
        __syncthreads();
#pragma unroll
        for (int ks = 0; ks < 2; ks++) {
            int kb = ks * 8;
            uint32_t a[2][4];
#pragma unroll
            for (int mi = 0; mi < 2; mi++) {
                a[mi][0] = f2tf32(Wsh[kb + t][wm + mi * 16 + g]);
                a[mi][1] = f2tf32(Wsh[kb + t][wm + mi * 16 + g + 8]);
                a[mi][2] = f2tf32(Wsh[kb + t + 4][wm + mi * 16 + g]);
                a[mi][3] = f2tf32(Wsh[kb + t + 4][wm + mi * 16 + g + 8]);
            }
#pragma unroll
            for (int ni = 0; ni < 4; ni++) {
                uint32_t b0 = f2tf32(Ish[kb + t][wn + ni * 8 + g]);
                uint32_t b1 = f2tf32(Ish[kb + t + 4][wn + ni * 8 + g]);
#pragma unroll
                for (int mi = 0; mi < 2; mi++)
                    mma_tf32(acc[mi][ni][0], acc[mi][ni][1], acc[mi][ni][2], acc[mi][ni][3],
                             a[mi][0], a[mi][1], a[mi][2], a[mi][3], b0, b1);
            }
        }
    }
    // epilogue
#pragma unroll
    for (int mi = 0; mi < 2; mi++) {
        int co0 = cb + wm + mi * 16 + g;
        int co1 = co0 + 8;
        float b0v = 0.f, b1v = 0.f, sc0 = 0.f, sc1 = 0.f, sh0 = 0.f, sh1 = 0.f;
        if (MODE == 0) {
            b0v = p0[co0];
            b1v = p0[co1];
        } else {
            sc0 = p0[co0] * rsqrtf(p3[co0] + 1e-5f);
            sh0 = p1[co0] - p2[co0] * sc0;
            sc1 = p0[co1] * rsqrtf(p3[co1] + 1e-5f);
            sh1 = p1[co1] - p2[co1] * sc1;
        }
        size_t row0 = ((size_t)b * Cout + co0) * HW + nbase;
        size_t row1 = ((size_t)b * Cout + co1) * HW + nbase;
#pragma unroll
        for (int ni = 0; ni < 4; ni++) {
            int x0 = wn + ni * 8 + 2 * t;
            float v00 = acc[mi][ni][0], v01 = acc[mi][ni][1];
            float v10 = acc[mi][ni][2], v11 = acc[mi][ni][3];
            if (MODE == 0) {
                v00 = hswish_f(v00 + b0v);
                v01 = hswish_f(v01 + b0v);
                v10 = hswish_f(v10 + b1v);
                v11 = hswish_f(v11 + b1v);
            } else {
                float2 r0 = *(const float2*)&res[row0 + x0];
                float2 r1 = *(const float2*)&res[row1 + x0];
                v00 = v00 * sc0 + sh0 + r0.x;
                v01 = v01 * sc0 + sh0 + r0.y;
                v10 = v10 * sc1 + sh1 + r1.x;
                v11 = v11 * sc1 + sh1 + r1.y;
            }
            *(float2*)&out[row0 + x0] = make_float2(v00, v01);
            *(float2*)&out[row1 + x0] = make_float2(v10, v11);
        }
    }
}

// ---------------- 5x5 depthwise on multi channels 0..383 -> msdw ----------------
__global__ void dw5x5_k(const float* __restrict__ in, const float* __restrict__ wgt,
                        float* __restrict__ out) {
    __shared__ float sh[5][136];
    int x = threadIdx.x;
    int y = blockIdx.x;
    int c = blockIdx.y;
    int b = blockIdx.z;
    const float* inC = in + ((size_t)b * 768 + c) * HW;
    for (int r = 0; r < 5; r++) {
        int yy = y - 2 + r;
        for (int i = x; i < 132; i += 128) {
            int xx = i - 2;
            float v = 0.f;
            if (yy >= 0 && yy < HH && xx >= 0 && xx < WW) v = inC[yy * WW + xx];
            sh[r][i] = v;
        }
    }
    __syncthreads();
    const float* wc = wgt + c * 25;
    float a = 0.f;
#pragma unroll
    for (int r = 0; r < 5; r++)
#pragma unroll
        for (int s = 0; s < 5; s++)
            a += wc[r * 5 + s] * sh[r][x + s];
    out[((size_t)b * 384 + c) * HW + y * WW + x] = a;
}

// ---------------- grouped 1x1, 8->8 per group, 48 groups; writes multi[384..767] ----------------
__global__ void pw_group_k(const float* __restrict__ in, const float* __restrict__ wgt,
                           float* __restrict__ out) {
    __shared__ float wsh[64];
    int g = blockIdx.y;
    int b = blockIdx.z;
    if (threadIdx.x < 64) wsh[threadIdx.x] = wgt[g * 64 + threadIdx.x];
    __syncthreads();
    int n = blockIdx.x * 128 + threadIdx.x;
    const float* ip = in + ((size_t)b * 384 + g * 8) * HW + n;
    float xi[8];
#pragma unroll
    for (int i = 0; i < 8; i++) xi[i] = ip[(size_t)i * HW];
    float* op = out + ((size_t)b * 768 + 384 + g * 8) * HW + n;
#pragma unroll
    for (int o = 0; o < 8; o++) {
        float a = 0.f;
#pragma unroll
        for (int i = 0; i < 8; i++) a += wsh[o * 8 + i] * xi[i];
        op[(size_t)o * HW] = a;
    }
}

// ---------------- zero kv accumulators ----------------
__global__ void zero_kv_k(float* __restrict__ kv) {
    int i = blockIdx.x * 256 + threadIdx.x;
    if (i < BB * 32 * 72) kv[i] = 0.f;
}

// ---------------- attention phase 1 ----------------
__global__ void attn_kv_k(const float* __restrict__ multi, float* __restrict__ kv) {
    int b = blockIdx.z, g = blockIdx.y;
    const float* base = multi + ((size_t)b * 768 + g * 24) * HW;
    int n0 = blockIdx.x * 2048;
    float acc[72];
#pragma unroll
    for (int i = 0; i < 72; i++) acc[i] = 0.f;
    for (int n = n0 + threadIdx.x; n < n0 + 2048; n += 256) {
        float kq[8], vv[8];
#pragma unroll
        for (int j = 0; j < 8; j++) kq[j] = fmaxf(base[(size_t)(8 + j) * HW + n], 0.f);
#pragma unroll
        for (int e = 0; e < 8; e++) vv[e] = base[(size_t)(16 + e) * HW + n];
#pragma unroll
        for (int e = 0; e < 8; e++)
#pragma unroll
            for (int j = 0; j < 8; j++) acc[e * 8 + j] += vv[e] * kq[j];
#pragma unroll
        for (int j = 0; j < 8; j++) acc[64 + j] += kq[j];
    }
    __shared__ float red[72][8];
    int lane = threadIdx.x & 31, warp = threadIdx.x >> 5;
#pragma unroll
    for (int i = 0; i < 72; i++) {
        float v = acc[i];
        v += __shfl_down_sync(0xffffffffu, v, 16);
        v += __shfl_down_sync(0xffffffffu, v, 8);
        v += __shfl_down_sync(0xffffffffu, v, 4);
        v += __shfl_down_sync(0xffffffffu, v, 2);
        v += __shfl_down_sync(0xffffffffu, v, 1);
        if (lane == 0) red[i][warp] = v;
    }
    __syncthreads();
    if (threadIdx.x < 72) {
        float s = 0.f;
#pragma unroll
        for (int w = 0; w < 8; w++) s += red[threadIdx.x][w];
        atomicAdd(&kv[((size_t)b * 32 + g) * 72 + threadIdx.x], s);
    }
}

// ---------------- attention phase 2 ----------------
__global__ void attn_apply_k(const float* __restrict__ multi, const float* __restrict__ kv,
                             float* __restrict__ att) {
    int b = blockIdx.z, g = blockIdx.y;
    __shared__ float kvs[72];
    if (threadIdx.x < 72) kvs[threadIdx.x] = kv[((size_t)b * 32 + g) * 72 + threadIdx.x];
    __syncthreads();
    int n = blockIdx.x * 256 + threadIdx.x;
    const float* base = multi + ((size_t)b * 768 + g * 24) * HW + n;
    float q[8];
#pragma unroll
    for (int j = 0; j < 8; j++) q[j] = fmaxf(base[(size_t)j * HW], 0.f);
    float denom = 0.f;
#pragma unroll
    for (int j = 0; j < 8; j++) denom += kvs[64 + j] * q[j];
    float inv = 1.f / (denom + 1e-15f);
    float* op = att + ((size_t)b * 256 + g * 8) * HW + n;
#pragma unroll
    for (int e = 0; e < 8; e++) {
        float s = 0.f;
#pragma unroll
        for (int j = 0; j < 8; j++) s += kvs[e * 8 + j] * q[j];
        op[(size_t)e * HW] = s * inv;
    }
}

// ---------------- 3x3 depthwise + bias + hswish (768 channels) ----------------
__global__ void dw3x3_k(const float* __restrict__ in, const float* __restrict__ wgt,
                        const float* __restrict__ bias, float* __restrict__ out) {
    __shared__ float sh[3][136];
    int x = threadIdx.x, y = blockIdx.x, c = blockIdx.y, b = blockIdx.z;
    const float* inC = in + ((size_t)b * 768 + c) * HW;
    for (int r = 0; r < 3; r++) {
        int yy = y - 1 + r;
        for (int i = x; i < 130; i += 128) {
            int xx = i - 1;
            float v = 0.f;
            if (yy >= 0 && yy < HH && xx >= 0 && xx < WW) v = inC[yy * WW + xx];
            sh[r][i] = v;
        }
    }
    __syncthreads();
    const float* wc = wgt + c * 9;
    float a = bias[c];
#pragma unroll
    for (int r = 0; r < 3; r++)
#pragma unroll
        for (int s = 0; s < 3; s++)
            a += wc[r * 3 + s] * sh[r][x + s];
    out[((size_t)b * 768 + c) * HW + y * WW + x] = hswish_f(a);
}

// ---------------- launch ----------------
extern "C" void kernel_launch(void* const* d_in, const int* in_sizes, int n_in,
                              void* d_out, int out_size) {
    const float* ref = (const float*)d_in[0];
    const float* oth = (const float*)d_in[1];
    const float* wq = (const float*)d_in[2];
    const float* bq = (const float*)d_in[3];
    const float* wk = (const float*)d_in[4];
    const float* bk = (const float*)d_in[5];
    const float* wv = (const float*)d_in[6];
    const float* bv = (const float*)d_in[7];
    const float* agg_dw_w = (const float*)d_in[8];
    const float* agg_pw_w = (const float*)d_in[9];
    const float* attn_proj_w = (const float*)d_in[10];
    const float* bn1_g = (const float*)d_in[11];
    const float* bn1_b = (const float*)d_in[12];
    const float* bn1_m = (const float*)d_in[13];
    const float* bn1_v = (const float*)d_in[14];
    const float* mb1_w = (const float*)d_in[15];
    const float* mb1_b = (const float*)d_in[16];
    const float* mb2_w = (const float*)d_in[17];
    const float* mb2_b = (const float*)d_in[18];
    const float* mb3_w = (const float*)d_in[19];
    const float* bn2_g = (const float*)d_in[20];
    const float* bn2_b = (const float*)d_in[21];
    const float* bn2_m = (const float*)d_in[22];
    const float* bn2_v = (const float*)d_in[23];

    float *multi, *msdw, *att, *attended, *h1, *h2, *kv, *wT;
    cudaGetSymbolAddress((void**)&multi, g_multi);
    cudaGetSymbolAddress((void**)&msdw, g_msdw);
    cudaGetSymbolAddress((void**)&att, g_att);
    cudaGetSymbolAddress((void**)&attended, g_attended);
    cudaGetSymbolAddress((void**)&h1, g_h1);
    cudaGetSymbolAddress((void**)&h2, g_h2);
    cudaGetSymbolAddress((void**)&kv, g_kv);
    cudaGetSymbolAddress((void**)&wT, g_wT);

    // q, k, v  (3x3 convs) -> multi channels 0/128/256
    transpose_k<<<(128 * 1152 + 255) / 256, 256>>>(wq, wT, 128, 1152);
    conv3x3_tc<<<dim3(128, 2, 4), 256>>>(ref, wT, bq, multi, 0);
    transpose_k<<<(128 * 1152 + 255) / 256, 256>>>(wk, wT, 128, 1152);
    conv3x3_tc<<<dim3(128, 2, 4), 256>>>(oth, wT, bk, multi, 128);
    transpose_k<<<(128 * 1152 + 255) / 256, 256>>>(wv, wT, 128, 1152);
    conv3x3_tc<<<dim3(128, 2, 4), 256>>>(oth, wT, bv, multi, 256);

    // aggregation: 5x5 dw then grouped 1x1 -> multi channels 384..767
    dw5x5_k<<<dim3(128, 384, 4), 128>>>(multi, agg_dw_w, msdw);
    pw_group_k<<<dim3(128, 48, 4), 128>>>(msdw, agg_pw_w, multi);

    // relu linear attention
    zero_kv_k<<<(BB * 32 * 72 + 255) / 256, 256>>>(kv);
    attn_kv_k<<<dim3(8, 32, 4), 256>>>(multi, kv);
    attn_apply_k<<<dim3(64, 32, 4), 256>>>(multi, kv, att);

    // attn_proj + bn1 + residual -> attended
    transpose_k<<<(128 * 256 + 255) / 256, 256>>>(attn_proj_w, wT, 128, 256);
    gemm1x1_tc<1><<<dim3(128, 2, 4), 256>>>(att, 256, wT, 128, bn1_g, bn1_b, bn1_m, bn1_v,
                                            ref, attended);

    // MBConv
    transpose_k<<<(768 * 128 + 255) / 256, 256>>>(mb1_w, wT, 768, 128);
    gemm1x1_tc<0><<<dim3(128, 12, 4), 256>>>(attended, 128, wT, 768, mb1_b, nullptr, nullptr,
                                             nullptr, nullptr, h1);
    dw3x3_k<<<dim3(128, 768, 4), 128>>>(h1, mb2_w, mb2_b, h2);
    transpose_k<<<(128 * 768 + 255) / 256, 256>>>(mb3_w, wT, 128, 768);
    gemm1x1_tc<1><<<dim3(128, 2, 4), 256>>>(h2, 768, wT, 128, bn2_g, bn2_b, bn2_m, bn2_v,
                                            attended, (float*)d_out);
}

// round 6
// speedup vs baseline: 1.9597x; 1.0810x over previous
#include <cuda_runtime.h>
#include <cstdint>
#include <cstddef>

#define HH 128
#define WW 128
#define HW 16384
#define BB 4

// ---------------- scratch (static device globals; no allocation) ----------------
__device__ float g_multi[(size_t)BB * 768 * HW];    // qkv (0..383) + ms (384..767)
__device__ float g_msdw[(size_t)BB * 384 * HW];     // depthwise 5x5 output
__device__ float g_att[(size_t)BB * 256 * HW];      // attention output
__device__ float g_attended[(size_t)BB * 128 * HW]; // residual branch point
__device__ float g_h1[(size_t)BB * 768 * HW];       // mb1 output
__device__ float g_h2[(size_t)BB * 768 * HW];       // mb2 output
__device__ float g_kv[(size_t)BB * 32 * 72];        // per-(b,g) 9x8 kv matrices
__device__ float g_wT[768 * 1152];                  // transposed weights scratch

// ---------------- tf32 mma helpers ----------------
__device__ __forceinline__ uint32_t f2tf32(float f) {
    uint32_t u;
    asm("cvt.rna.tf32.f32 %0, %1;" : "=r"(u) : "f"(f));
    return u;
}

__device__ __forceinline__ float f2tf32f(float f) {
    uint32_t u;
    asm("cvt.rna.tf32.f32 %0, %1;" : "=r"(u) : "f"(f));
    return __uint_as_float(u);
}

__device__ __forceinline__ void mma_tf32(float& d0, float& d1, float& d2, float& d3,
                                         uint32_t a0, uint32_t a1, uint32_t a2, uint32_t a3,
                                         uint32_t b0, uint32_t b1) {
    asm volatile(
        "mma.sync.aligned.m16n8k8.row.col.f32.tf32.tf32.f32 "
        "{%0,%1,%2,%3},{%4,%5,%6,%7},{%8,%9},{%0,%1,%2,%3};"
        : "+f"(d0), "+f"(d1), "+f"(d2), "+f"(d3)
        : "r"(a0), "r"(a1), "r"(a2), "r"(a3), "r"(b0), "r"(b1));
}

__device__ __forceinline__ float hswish_f(float x) {
    return x * fminf(fmaxf(x + 3.f, 0.f), 6.f) * (1.f / 6.f);
}

// ---------------- weight transpose: w[co][k] -> wT[k][co] ----------------
__global__ void transpose_k(const float* __restrict__ w, float* __restrict__ wT,
                            int Cout, int Cin) {
    int idx = blockIdx.x * 256 + threadIdx.x;
    if (idx < Cout * Cin) {
        int co = idx / Cin;
        int ci = idx - co * Cin;
        wT[(size_t)ci * Cout + co] = w[idx];
    }
}

// ---------------- fused 3x3 convs (q,k,v) via tf32 tensor cores ----------------
// blockIdx.y in [0,6): cv = y>>1 selects conv (0=q on ref, 1=k, 2=v on oth),
// cbase = (y&1)*64. Smem tiles hold tf32 bit patterns (pre-converted at fill).
__global__ void conv3x3_tc(const float* __restrict__ ref, const float* __restrict__ oth,
                           const float* __restrict__ wTall,
                           const float* __restrict__ bq, const float* __restrict__ bk,
                           const float* __restrict__ bv, float* __restrict__ out) {
    __shared__ float Wsh[72][72];       // [cin8*9+rs][cout64 pad72]
    __shared__ float Ish[8][3][136];    // [cin8][row3][col(-1..128) pad]
    int tid = threadIdx.x;
    int lane = tid & 31, warp = tid >> 5;
    int g = lane >> 2, t = lane & 3;
    int wm = (warp >> 2) * 32;          // warp M offset (0/32)
    int wn = (warp & 3) * 32;           // warp N offset (0..96)
    int y = blockIdx.x;
    int cv = blockIdx.y >> 1;
    int cbase = (blockIdx.y & 1) * 64;
    int b = blockIdx.z;
    const float* in = (cv == 0) ? ref : oth;
    const float* wT = wTall + (size_t)cv * 1152 * 128;
    const float* bias = (cv == 0) ? bq : (cv == 1) ? bk : bv;
    int outOff = cv * 128;
    const float* inB = in + (size_t)b * 128 * HW;
    float acc[2][4][4] = {};

    for (int c0 = 0; c0 < 128; c0 += 8) {
        __syncthreads();
        for (int i = tid; i < 72 * 64; i += 256) {
            int k = i >> 6, oc = i & 63;
            Wsh[k][oc] = f2tf32f(wT[(size_t)(c0 * 9 + k) * 128 + cbase + oc]);
        }
        for (int i = tid; i < 8 * 3 * 130; i += 256) {
            int col = i % 130;
            int tr = i / 130;
            int r = tr % 3, c = tr / 3;
            int xx = col - 1, yy = y - 1 + r;
            float v = 0.f;
            if (xx >= 0 && xx < WW && yy >= 0 && yy < HH)
                v = inB[(size_t)(c0 + c) * HW + yy * WW + xx];
            Ish[c][r][col] = f2tf32f(v);
        }
        __syncthreads();
#pragma unroll
        for (int r = 0; r < 3; r++) {
#pragma unroll
            for (int s = 0; s < 3; s++) {
                int rs = r * 3 + s;
                uint32_t a[2][4];
#pragma unroll
                for (int mi = 0; mi < 2; mi++) {
                    a[mi][0] = __float_as_uint(Wsh[t * 9 + rs][wm + mi * 16 + g]);
                    a[mi][1] = __float_as_uint(Wsh[t * 9 + rs][wm + mi * 16 + g + 8]);
                    a[mi][2] = __float_as_uint(Wsh[(t + 4) * 9 + rs][wm + mi * 16 + g]);
                    a[mi][3] = __float_as_uint(Wsh[(t + 4) * 9 + rs][wm + mi * 16 + g + 8]);
                }
#pragma unroll
                for (int ni = 0; ni < 4; ni++) {
                    uint32_t b0 = __float_as_uint(Ish[t][r][wn + ni * 8 + g + s]);
                    uint32_t b1 = __float_as_uint(Ish[t + 4][r][wn + ni * 8 + g + s]);
#pragma unroll
                    for (int mi = 0; mi < 2; mi++)
                        mma_tf32(acc[mi][ni][0], acc[mi][ni][1], acc[mi][ni][2], acc[mi][ni][3],
                                 a[mi][0], a[mi][1], a[mi][2], a[mi][3], b0, b1);
                }
            }
        }
    }
#pragma unroll
    for (int mi = 0; mi < 2; mi++) {
        int co0 = cbase + wm + mi * 16 + g;
        int co1 = co0 + 8;
        float bv0 = bias[co0], bv1 = bias[co1];
        float* p0 = out + ((size_t)b * 768 + outOff + co0) * HW + y * WW;
        float* p1 = out + ((size_t)b * 768 + outOff + co1) * HW + y * WW;
#pragma unroll
        for (int ni = 0; ni < 4; ni++) {
            int x0 = wn + ni * 8 + 2 * t;
            *(float2*)&p0[x0] = make_float2(acc[mi][ni][0] + bv0, acc[mi][ni][1] + bv0);
            *(float2*)&p1[x0] = make_float2(acc[mi][ni][2] + bv1, acc[mi][ni][3] + bv1);
        }
    }
}

// ---------------- 1x1 conv (GEMM) via tf32 tensor cores ----------------
// Block: 64 couts x 128 pixels. MODE 0: hswish(acc+bias). MODE 1: res + bn(acc).
// Smem tiles hold tf32 bit patterns.
template <int MODE>
__global__ void gemm1x1_tc(const float* __restrict__ in, int Cin,
                           const float* __restrict__ wT, int Cout,
                           const float* __restrict__ p0, const float* __restrict__ p1,
                           const float* __restrict__ p2, const float* __restrict__ p3,
                           const float* __restrict__ res, float* __restrict__ out) {
    __shared__ float Wsh[16][72];
    __shared__ float Ish[16][136];
    int tid = threadIdx.x;
    int lane = tid & 31, warp = tid >> 5;
    int g = lane >> 2, t = lane & 3;
    int wm = (warp >> 2) * 32;
    int wn = (warp & 3) * 32;
    int nbase = blockIdx.x * 128;
    int cb = blockIdx.y * 64;
    int b = blockIdx.z;
    const float* inB = in + (size_t)b * Cin * HW + nbase;
    float acc[2][4][4] = {};

    for (int k0 = 0; k0 < Cin; k0 += 16) {
        __syncthreads();
        {
            int k = tid >> 4, p = tid & 15;
            float4 wv = *(const float4*)&wT[(size_t)(k0 + k) * Cout + cb + p * 4];
            wv.x = f2tf32f(wv.x); wv.y = f2tf32f(wv.y);
            wv.z = f2tf32f(wv.z); wv.w = f2tf32f(wv.w);
            *(float4*)&Wsh[k][p * 4] = wv;
            int k2 = tid >> 5, p2 = tid & 31;
            float4 iv = *(const float4*)&inB[(size_t)(k0 + k2) * HW + p2 * 4];
            iv.x = f2tf32f(iv.x); iv.y = f2tf32f(iv.y);
            iv.z = f2tf32f(iv.z); iv.w = f2tf32f(iv.w);
            *(float4*)&Ish[k2][p2 * 4] = iv;
            float4 iv2 = *(const float4*)&inB[(size_t)(k0 + k2 + 8) * HW + p2 * 4];
            iv2.x = f2tf32f(iv2.x); iv2.y = f2tf32f(iv2.y);
            iv2.z = f2tf32f(iv2.z); iv2.w = f2tf32f(iv2.w);
            *(float4*)&Ish[k2 + 8][p2 * 4] = iv2;
        }
        __syncthreads();
#pragma unroll
        for (int ks = 0; ks < 2; ks++) {
            int kb = ks * 8;
            uint32_t a[2][4];
#pragma unroll
            for (int mi = 0; mi < 2; mi++) {
                a[mi][0] = __float_as_uint(Wsh[kb + t][wm + mi * 16 + g]);
                a[mi][1] = __float_as_uint(Wsh[kb + t][wm + mi * 16 + g + 8]);
                a[mi][2] = __float_as_uint(Wsh[kb + t + 4][wm + mi * 16 + g]);
                a[mi][3] = __float_as_uint(Wsh[kb + t + 4][wm + mi * 16 + g + 8]);
            }
#pragma unroll
            for (int ni = 0; ni < 4; ni++) {
                uint32_t b0 = __float_as_uint(Ish[kb + t][wn + ni * 8 + g]);
                uint32_t b1 = __float_as_uint(Ish[kb + t + 4][wn + ni * 8 + g]);
#pragma unroll
                for (int mi = 0; mi < 2; mi++)
                    mma_tf32(acc[mi][ni][0], acc[mi][ni][1], acc[mi][ni][2], acc[mi][ni][3],
                             a[mi][0], a[mi][1], a[mi][2], a[mi][3], b0, b1);
            }
        }
    }
    // epilogue
#pragma unroll
    for (int mi = 0; mi < 2; mi++) {
        int co0 = cb + wm + mi * 16 + g;
        int co1 = co0 + 8;
        float b0v = 0.f, b1v = 0.f, sc0 = 0.f, sc1 = 0.f, sh0 = 0.f, sh1 = 0.f;
        if (MODE == 0) {
            b0v = p0[co0];
            b1v = p0[co1];
        } else {
            sc0 = p0[co0] * rsqrtf(p3[co0] + 1e-5f);
            sh0 = p1[co0] - p2[co0] * sc0;
            sc1 = p0[co1] * rsqrtf(p3[co1] + 1e-5f);
            sh1 = p1[co1] - p2[co1] * sc1;
        }
        size_t row0 = ((size_t)b * Cout + co0) * HW + nbase;
        size_t row1 = ((size_t)b * Cout + co1) * HW + nbase;
#pragma unroll
        for (int ni = 0; ni < 4; ni++) {
            int x0 = wn + ni * 8 + 2 * t;
            float v00 = acc[mi][ni][0], v01 = acc[mi][ni][1];
            float v10 = acc[mi][ni][2], v11 = acc[mi][ni][3];
            if (MODE == 0) {
                v00 = hswish_f(v00 + b0v);
                v01 = hswish_f(v01 + b0v);
                v10 = hswish_f(v10 + b1v);
                v11 = hswish_f(v11 + b1v);
            } else {
                float2 r0 = *(const float2*)&res[row0 + x0];
                float2 r1 = *(const float2*)&res[row1 + x0];
                v00 = v00 * sc0 + sh0 + r0.x;
                v01 = v01 * sc0 + sh0 + r0.y;
                v10 = v10 * sc1 + sh1 + r1.x;
                v11 = v11 * sc1 + sh1 + r1.y;
            }
            *(float2*)&out[row0 + x0] = make_float2(v00, v01);
            *(float2*)&out[row1 + x0] = make_float2(v10, v11);
        }
    }
}

// ---------------- 5x5 depthwise on multi channels 0..383 -> msdw ----------------
__global__ void dw5x5_k(const float* __restrict__ in, const float* __restrict__ wgt,
                        float* __restrict__ out) {
    __shared__ float sh[5][136];
    int x = threadIdx.x;
    int y = blockIdx.x;
    int c = blockIdx.y;
    int b = blockIdx.z;
    const float* inC = in + ((size_t)b * 768 + c) * HW;
    for (int r = 0; r < 5; r++) {
        int yy = y - 2 + r;
        for (int i = x; i < 132; i += 128) {
            int xx = i - 2;
            float v = 0.f;
            if (yy >= 0 && yy < HH && xx >= 0 && xx < WW) v = inC[yy * WW + xx];
            sh[r][i] = v;
        }
    }
    __syncthreads();
    const float* wc = wgt + c * 25;
    float a = 0.f;
#pragma unroll
    for (int r = 0; r < 5; r++)
#pragma unroll
        for (int s = 0; s < 5; s++)
            a += wc[r * 5 + s] * sh[r][x + s];
    out[((size_t)b * 384 + c) * HW + y * WW + x] = a;
}

// ---------------- grouped 1x1, 8->8 per group, 48 groups; writes multi[384..767] ----------------
__global__ void pw_group_k(const float* __restrict__ in, const float* __restrict__ wgt,
                           float* __restrict__ out) {
    __shared__ float wsh[64];
    int g = blockIdx.y;
    int b = blockIdx.z;
    if (threadIdx.x < 64) wsh[threadIdx.x] = wgt[g * 64 + threadIdx.x];
    __syncthreads();
    int n = blockIdx.x * 128 + threadIdx.x;
    const float* ip = in + ((size_t)b * 384 + g * 8) * HW + n;
    float xi[8];
#pragma unroll
    for (int i = 0; i < 8; i++) xi[i] = ip[(size_t)i * HW];
    float* op = out + ((size_t)b * 768 + 384 + g * 8) * HW + n;
#pragma unroll
    for (int o = 0; o < 8; o++) {
        float a = 0.f;
#pragma unroll
        for (int i = 0; i < 8; i++) a += wsh[o * 8 + i] * xi[i];
        op[(size_t)o * HW] = a;
    }
}

// ---------------- zero kv accumulators ----------------
__global__ void zero_kv_k(float* __restrict__ kv) {
    int i = blockIdx.x * 256 + threadIdx.x;
    if (i < BB * 32 * 72) kv[i] = 0.f;
}

// ---------------- attention phase 1 ----------------
__global__ void attn_kv_k(const float* __restrict__ multi, float* __restrict__ kv) {
    int b = blockIdx.z, g = blockIdx.y;
    const float* base = multi + ((size_t)b * 768 + g * 24) * HW;
    int n0 = blockIdx.x * 2048;
    float acc[72];
#pragma unroll
    for (int i = 0; i < 72; i++) acc[i] = 0.f;
    for (int n = n0 + threadIdx.x; n < n0 + 2048; n += 256) {
        float kq[8], vv[8];
#pragma unroll
        for (int j = 0; j < 8; j++) kq[j] = fmaxf(base[(size_t)(8 + j) * HW + n], 0.f);
#pragma unroll
        for (int e = 0; e < 8; e++) vv[e] = base[(size_t)(16 + e) * HW + n];
#pragma unroll
        for (int e = 0; e < 8; e++)
#pragma unroll
            for (int j = 0; j < 8; j++) acc[e * 8 + j] += vv[e] * kq[j];
#pragma unroll
        for (int j = 0; j < 8; j++) acc[64 + j] += kq[j];
    }
    __shared__ float red[72][8];
    int lane = threadIdx.x & 31, warp = threadIdx.x >> 5;
#pragma unroll
    for (int i = 0; i < 72; i++) {
        float v = acc[i];
        v += __shfl_down_sync(0xffffffffu, v, 16);
        v += __shfl_down_sync(0xffffffffu, v, 8);
        v += __shfl_down_sync(0xffffffffu, v, 4);
        v += __shfl_down_sync(0xffffffffu, v, 2);
        v += __shfl_down_sync(0xffffffffu, v, 1);
        if (lane == 0) red[i][warp] = v;
    }
    __syncthreads();
    if (threadIdx.x < 72) {
        float s = 0.f;
#pragma unroll
        for (int w = 0; w < 8; w++) s += red[threadIdx.x][w];
        atomicAdd(&kv[((size_t)b * 32 + g) * 72 + threadIdx.x], s);
    }
}

// ---------------- attention phase 2 ----------------
__global__ void attn_apply_k(const float* __restrict__ multi, const float* __restrict__ kv,
                             float* __restrict__ att) {
    int b = blockIdx.z, g = blockIdx.y;
    __shared__ float kvs[72];
    if (threadIdx.x < 72) kvs[threadIdx.x] = kv[((size_t)b * 32 + g) * 72 + threadIdx.x];
    __syncthreads();
    int n = blockIdx.x * 256 + threadIdx.x;
    const float* base = multi + ((size_t)b * 768 + g * 24) * HW + n;
    float q[8];
#pragma unroll
    for (int j = 0; j < 8; j++) q[j] = fmaxf(base[(size_t)j * HW], 0.f);
    float denom = 0.f;
#pragma unroll
    for (int j = 0; j < 8; j++) denom += kvs[64 + j] * q[j];
    float inv = 1.f / (denom + 1e-15f);
    float* op = att + ((size_t)b * 256 + g * 8) * HW + n;
#pragma unroll
    for (int e = 0; e < 8; e++) {
        float s = 0.f;
#pragma unroll
        for (int j = 0; j < 8; j++) s += kvs[e * 8 + j] * q[j];
        op[(size_t)e * HW] = s * inv;
    }
}

// ---------------- 3x3 depthwise + bias + hswish (768 channels) ----------------
__global__ void dw3x3_k(const float* __restrict__ in, const float* __restrict__ wgt,
                        const float* __restrict__ bias, float* __restrict__ out) {
    __shared__ float sh[3][136];
    int x = threadIdx.x, y = blockIdx.x, c = blockIdx.y, b = blockIdx.z;
    const float* inC = in + ((size_t)b * 768 + c) * HW;
    for (int r = 0; r < 3; r++) {
        int yy = y - 1 + r;
        for (int i = x; i < 130; i += 128) {
            int xx = i - 1;
            float v = 0.f;
            if (yy >= 0 && yy < HH && xx >= 0 && xx < WW) v = inC[yy * WW + xx];
            sh[r][i] = v;
        }
    }
    __syncthreads();
    const float* wc = wgt + c * 9;
    float a = bias[c];
#pragma unroll
    for (int r = 0; r < 3; r++)
#pragma unroll
        for (int s = 0; s < 3; s++)
            a += wc[r * 3 + s] * sh[r][x + s];
    out[((size_t)b * 768 + c) * HW + y * WW + x] = hswish_f(a);
}

// ---------------- launch ----------------
extern "C" void kernel_launch(void* const* d_in, const int* in_sizes, int n_in,
                              void* d_out, int out_size) {
    const float* ref = (const float*)d_in[0];
    const float* oth = (const float*)d_in[1];
    const float* wq = (const float*)d_in[2];
    const float* bq = (const float*)d_in[3];
    const float* wk = (const float*)d_in[4];
    const float* bk = (const float*)d_in[5];
    const float* wv = (const float*)d_in[6];
    const float* bv = (const float*)d_in[7];
    const float* agg_dw_w = (const float*)d_in[8];
    const float* agg_pw_w = (const float*)d_in[9];
    const float* attn_proj_w = (const float*)d_in[10];
    const float* bn1_g = (const float*)d_in[11];
    const float* bn1_b = (const float*)d_in[12];
    const float* bn1_m = (const float*)d_in[13];
    const float* bn1_v = (const float*)d_in[14];
    const float* mb1_w = (const float*)d_in[15];
    const float* mb1_b = (const float*)d_in[16];
    const float* mb2_w = (const float*)d_in[17];
    const float* mb2_b = (const float*)d_in[18];
    const float* mb3_w = (const float*)d_in[19];
    const float* bn2_g = (const float*)d_in[20];
    const float* bn2_b = (const float*)d_in[21];
    const float* bn2_m = (const float*)d_in[22];
    const float* bn2_v = (const float*)d_in[23];

    float *multi, *msdw, *att, *attended, *h1, *h2, *kv, *wT;
    cudaGetSymbolAddress((void**)&multi, g_multi);
    cudaGetSymbolAddress((void**)&msdw, g_msdw);
    cudaGetSymbolAddress((void**)&att, g_att);
    cudaGetSymbolAddress((void**)&attended, g_attended);
    cudaGetSymbolAddress((void**)&h1, g_h1);
    cudaGetSymbolAddress((void**)&h2, g_h2);
    cudaGetSymbolAddress((void**)&kv, g_kv);
    cudaGetSymbolAddress((void**)&wT, g_wT);

    // transpose all three qkv weight sets into disjoint wT regions
    transpose_k<<<(128 * 1152 + 255) / 256, 256>>>(wq, wT, 128, 1152);
    transpose_k<<<(128 * 1152 + 255) / 256, 256>>>(wk, wT + 1152 * 128, 128, 1152);
    transpose_k<<<(128 * 1152 + 255) / 256, 256>>>(wv, wT + 2 * 1152 * 128, 128, 1152);
    // fused q,k,v 3x3 convs -> multi channels 0/128/256
    conv3x3_tc<<<dim3(128, 6, 4), 256>>>(ref, oth, wT, bq, bk, bv, multi);

    // aggregation: 5x5 dw then grouped 1x1 -> multi channels 384..767
    dw5x5_k<<<dim3(128, 384, 4), 128>>>(multi, agg_dw_w, msdw);
    pw_group_k<<<dim3(128, 48, 4), 128>>>(msdw, agg_pw_w, multi);

    // relu linear attention
    zero_kv_k<<<(BB * 32 * 72 + 255) / 256, 256>>>(kv);
    attn_kv_k<<<dim3(8, 32, 4), 256>>>(multi, kv);
    attn_apply_k<<<dim3(64, 32, 4), 256>>>(multi, kv, att);

    // attn_proj + bn1 + residual -> attended
    transpose_k<<<(128 * 256 + 255) / 256, 256>>>(attn_proj_w, wT, 128, 256);
    gemm1x1_tc<1><<<dim3(128, 2, 4), 256>>>(att, 256, wT, 128, bn1_g, bn1_b, bn1_m, bn1_v,
                                            ref, attended);

    // MBConv
    transpose_k<<<(768 * 128 + 255) / 256, 256>>>(mb1_w, wT, 768, 128);
    gemm1x1_tc<0><<<dim3(128, 12, 4), 256>>>(attended, 128, wT, 768, mb1_b, nullptr, nullptr,
                                             nullptr, nullptr, h1);
    dw3x3_k<<<dim3(128, 768, 4), 128>>>(h1, mb2_w, mb2_b, h2);
    transpose_k<<<(128 * 768 + 255) / 256, 256>>>(mb3_w, wT, 128, 768);
    gemm1x1_tc<1><<<dim3(128, 2, 4), 256>>>(h2, 768, wT, 128, bn2_g, bn2_b, bn2_m, bn2_v,
                                            attended, (float*)d_out);
}